// round 7
// baseline (speedup 1.0000x reference)
#include <cuda_runtime.h>

#define T_STEPS 512
#define BATCH   32
#define IDIM    1024
#define HDIM    1024
#define G4      4096   // 4*HDIM
#define GRID_SCAN 128  // must be <= SM count; all CTAs co-resident

// Scratch (static device arrays: allowed; no cudaMalloc anywhere)
__device__ float g_gates[(size_t)T_STEPS * BATCH * G4];   // [t*B+b][g]  (256 MB)
__device__ float g_part[4 * BATCH * G4];                  // [kc][b][g]  (2 MB)

// Grid-barrier state. Sense-reversing: after an EVEN number of barriers
// (2 per step * 512 = 1024) both return to {0,0}, so graph replays are clean.
__device__ int               g_bar_count = 0;
__device__ volatile unsigned g_bar_sense = 0;

__device__ __forceinline__ float hsig(float x) {
    return fminf(fmaxf(x * (1.0f / 6.0f) + 0.5f, 0.0f), 1.0f);
}
__device__ __forceinline__ float htanh(float x) {
    return fminf(fmaxf(x, -1.0f), 1.0f);
}

__device__ __forceinline__ void grid_barrier(unsigned* local_sense) {
    __threadfence();          // all this thread's global writes -> visible device-wide
    __syncthreads();          // all threads of CTA have fenced
    if (threadIdx.x == 0) {
        const unsigned s = *local_sense ^ 1u;
        *local_sense = s;
        if (atomicAdd(&g_bar_count, 1) == GRID_SCAN - 1) {
            g_bar_count = 0;  // safe: everyone has arrived, nobody is adding
            __threadfence();
            g_bar_sense = s;  // release
        } else {
            while (g_bar_sense != s) { }
        }
    }
    __syncthreads();
}

// ---------------------------------------------------------------------------
// Kernel A: gates_pre[m][n] = sum_k x[m][k]*W[n][k] + (bW[n]+bR[n])
// M=16384, N=4096, K=1024.  BM=BN=128, BK=16, 8x8 per thread, 256 threads.
// ---------------------------------------------------------------------------
__global__ __launch_bounds__(256) void gemm_gates(
    const float* __restrict__ x, const float* __restrict__ W,
    const float* __restrict__ bW, const float* __restrict__ bR)
{
    const int BK = 16;
    __shared__ float As[BK][128 + 4];
    __shared__ float Bs[BK][128 + 4];

    const int tid  = threadIdx.x;
    const int mblk = blockIdx.y;   // 0..127
    const int nblk = blockIdx.x;   // 0..31

    const float* Ab = x + (size_t)mblk * 128 * IDIM;
    const float* Bb = W + (size_t)nblk * 128 * IDIM;

    const int lrow = tid >> 2;          // 0..63
    const int lcol = (tid & 3) * 4;     // 0,4,8,12

    const int ty = tid >> 4;            // 0..15
    const int tx = tid & 15;            // 0..15
    const int m0 = ty * 8;
    const int n0 = tx * 8;

    float acc[8][8];
#pragma unroll
    for (int i = 0; i < 8; i++)
#pragma unroll
        for (int j = 0; j < 8; j++) acc[i][j] = 0.0f;

    for (int k0 = 0; k0 < IDIM; k0 += BK) {
        float4 a0 = *(const float4*)(Ab + (size_t)lrow        * IDIM + k0 + lcol);
        float4 a1 = *(const float4*)(Ab + (size_t)(lrow + 64) * IDIM + k0 + lcol);
        float4 b0 = *(const float4*)(Bb + (size_t)lrow        * IDIM + k0 + lcol);
        float4 b1 = *(const float4*)(Bb + (size_t)(lrow + 64) * IDIM + k0 + lcol);

        __syncthreads();
        As[lcol + 0][lrow] = a0.x; As[lcol + 1][lrow] = a0.y;
        As[lcol + 2][lrow] = a0.z; As[lcol + 3][lrow] = a0.w;
        As[lcol + 0][lrow + 64] = a1.x; As[lcol + 1][lrow + 64] = a1.y;
        As[lcol + 2][lrow + 64] = a1.z; As[lcol + 3][lrow + 64] = a1.w;
        Bs[lcol + 0][lrow] = b0.x; Bs[lcol + 1][lrow] = b0.y;
        Bs[lcol + 2][lrow] = b0.z; Bs[lcol + 3][lrow] = b0.w;
        Bs[lcol + 0][lrow + 64] = b1.x; Bs[lcol + 1][lrow + 64] = b1.y;
        Bs[lcol + 2][lrow + 64] = b1.z; Bs[lcol + 3][lrow + 64] = b1.w;
        __syncthreads();

#pragma unroll
        for (int k = 0; k < BK; k++) {
            float4 av0 = *(const float4*)&As[k][m0];
            float4 av1 = *(const float4*)&As[k][m0 + 4];
            float4 bv0 = *(const float4*)&Bs[k][n0];
            float4 bv1 = *(const float4*)&Bs[k][n0 + 4];
            float a[8] = {av0.x, av0.y, av0.z, av0.w, av1.x, av1.y, av1.z, av1.w};
            float b[8] = {bv0.x, bv0.y, bv0.z, bv0.w, bv1.x, bv1.y, bv1.z, bv1.w};
#pragma unroll
            for (int i = 0; i < 8; i++)
#pragma unroll
                for (int j = 0; j < 8; j++) acc[i][j] += a[i] * b[j];
        }
    }

#pragma unroll
    for (int j = 0; j < 8; j++) {
        const int n = nblk * 128 + n0 + j;
        const float bias = bW[n] + bR[n];
#pragma unroll
        for (int i = 0; i < 8; i++) {
            const int m = mblk * 128 + m0 + i;
            g_gates[(size_t)m * G4 + n] = acc[i][j] + bias;
        }
    }
}

// ---------------------------------------------------------------------------
// Kernel B: persistent scan. grid = 128 CTAs x 256 threads.
// Per step:
//   phase 1 (GEMM): CTA (mblk = bid&31, kc = bid>>5) computes
//     part[kc][b][g] = sum_{k in kc-chunk} R[g][k] * y_prev[b][k]
//     for g in [mblk*128, mblk*128+128), b in [0,32). 4x4 per-thread tile.
//   barrier
//   phase 2 (combine): flat thread n = bid*256+tid handles (b,h):
//     sum 4 partials + gates_pre, hard nonlinearities, cell update, write y/c.
//   barrier
// Cross-CTA-written data read with __ldcg (L1 bypass); R / g_gates stay on L1
// (L1D persists across steps inside one launch -> R chunk becomes L1-resident).
// ---------------------------------------------------------------------------
__global__ __launch_bounds__(256) void lstm_scan(
    const float* __restrict__ R, const float* __restrict__ y0,
    const float* __restrict__ c0, float* __restrict__ yout,
    float* __restrict__ cout)
{
    const int BK = 16, KC = 256;
    __shared__ float Rs[BK][128 + 4];
    __shared__ float Ys[BK][32 + 4];
    __shared__ unsigned bar_sense;

    const int tid  = threadIdx.x;
    const int bid  = blockIdx.x;
    const int mblk = bid & 31;     // g-tile 0..31
    const int kc   = bid >> 5;     // k-chunk 0..3

    if (tid == 0) bar_sense = 0;

    const int lrow = tid >> 2;         // 0..63
    const int lcol = (tid & 3) * 4;    // 0,4,8,12
    const int m0   = (tid & 31) * 4;   // 0..124
    const int n0   = (tid >> 5) * 4;   // 0..28

    const float* Rb = R + (size_t)mblk * 128 * HDIM + kc * KC;
    float* part = g_part + (size_t)kc * BATCH * G4;

    // combine-phase indexing
    const int cn = bid * 256 + tid;    // 0..32767
    const int cb = cn >> 10;           // batch
    const int ch = cn & 1023;          // hidden

    for (int t = 0; t < T_STEPS; t++) {
        const float* yprev = t ? (yout + (size_t)(t - 1) * BATCH * HDIM) : y0;
        const float* Yb = yprev + kc * KC;

        // -------- phase 1: recurrent GEMM partial --------
        float acc[4][4];
#pragma unroll
        for (int i = 0; i < 4; i++)
#pragma unroll
            for (int j = 0; j < 4; j++) acc[i][j] = 0.0f;

        for (int k0 = 0; k0 < KC; k0 += BK) {
            float4 r0 = __ldg((const float4*)(Rb + (size_t)lrow        * HDIM + k0 + lcol));
            float4 r1 = __ldg((const float4*)(Rb + (size_t)(lrow + 64) * HDIM + k0 + lcol));
            float4 yv = make_float4(0.f, 0.f, 0.f, 0.f);
            const bool yload = (tid < 128);
            if (yload)
                yv = __ldcg((const float4*)(Yb + (size_t)(tid >> 2) * HDIM + k0 + (tid & 3) * 4));

            __syncthreads();
            Rs[lcol + 0][lrow] = r0.x; Rs[lcol + 1][lrow] = r0.y;
            Rs[lcol + 2][lrow] = r0.z; Rs[lcol + 3][lrow] = r0.w;
            Rs[lcol + 0][lrow + 64] = r1.x; Rs[lcol + 1][lrow + 64] = r1.y;
            Rs[lcol + 2][lrow + 64] = r1.z; Rs[lcol + 3][lrow + 64] = r1.w;
            if (yload) {
                const int yr = tid >> 2, yc = (tid & 3) * 4;
                Ys[yc + 0][yr] = yv.x; Ys[yc + 1][yr] = yv.y;
                Ys[yc + 2][yr] = yv.z; Ys[yc + 3][yr] = yv.w;
            }
            __syncthreads();

#pragma unroll
            for (int k = 0; k < BK; k++) {
                float4 a = *(const float4*)&Rs[k][m0];
                float4 b = *(const float4*)&Ys[k][n0];
                float av[4] = {a.x, a.y, a.z, a.w};
                float bv[4] = {b.x, b.y, b.z, b.w};
#pragma unroll
                for (int i = 0; i < 4; i++)
#pragma unroll
                    for (int j = 0; j < 4; j++) acc[i][j] += av[i] * bv[j];
            }
        }

#pragma unroll
        for (int j = 0; j < 4; j++) {
            const int b = n0 + j;
#pragma unroll
            for (int i = 0; i < 4; i++) {
                const int g = mblk * 128 + m0 + i;
                part[(size_t)b * G4 + g] = acc[i][j];
            }
        }

        grid_barrier(&bar_sense);

        // -------- phase 2: combine + nonlinearities + state update --------
        {
            const float* gb = g_gates + ((size_t)t * BATCH + cb) * G4;
            float gi = __ldg(gb + ch);
            float gf = __ldg(gb + HDIM + ch);
            float gz = __ldg(gb + 2 * HDIM + ch);
            float go = __ldg(gb + 3 * HDIM + ch);

#pragma unroll
            for (int c = 0; c < 4; c++) {
                const float* p = g_part + (size_t)c * BATCH * G4 + (size_t)cb * G4;
                gi += __ldcg(p + ch);
                gf += __ldcg(p + HDIM + ch);
                gz += __ldcg(p + 2 * HDIM + ch);
                go += __ldcg(p + 3 * HDIM + ch);
            }

            const float* cprev = t ? (cout + (size_t)(t - 1) * BATCH * HDIM) : c0;
            const float cp = __ldcg(cprev + cn);

            const float i_ = hsig(gi);
            const float f_ = hsig(gf);
            const float z_ = htanh(gz);
            const float o_ = hsig(go);

            const float c_new = f_ * cp + i_ * z_;
            const float y_new = o_ * htanh(c_new);

            yout[(size_t)t * BATCH * HDIM + cn] = y_new;
            cout[(size_t)t * BATCH * HDIM + cn] = c_new;
        }

        grid_barrier(&bar_sense);
    }
}

// ---------------------------------------------------------------------------
// Launch: exactly 2 graph nodes.
// ---------------------------------------------------------------------------
extern "C" void kernel_launch(void* const* d_in, const int* in_sizes, int n_in,
                              void* d_out, int out_size)
{
    const float* y0 = (const float*)d_in[0];
    const float* c0 = (const float*)d_in[1];
    const float* x  = (const float*)d_in[2];
    const float* W  = (const float*)d_in[3];
    const float* R  = (const float*)d_in[4];
    const float* bW = (const float*)d_in[5];
    const float* bR = (const float*)d_in[6];

    float* yout = (float*)d_out;                                   // [T,B,H]
    float* cout = yout + (size_t)T_STEPS * BATCH * HDIM;           // [T,B,H]

    // Input projection for all timesteps (node 1)
    gemm_gates<<<dim3(32, 128), 256>>>(x, W, bW, bR);

    // Full sequential scan in one persistent kernel (node 2)
    lstm_scan<<<GRID_SCAN, 256>>>(R, y0, c0, yout, cout);
}

// round 12
// speedup vs baseline: 2.2322x; 2.2322x over previous
#include <cuda_runtime.h>
#include <cuda_bf16.h>
#include <cstdint>

#define T_STEPS 512
#define BATCH   32
#define IDIM    1024
#define HDIM    1024
#define G4      4096   // 4*HDIM
#define GRID_SCAN 128  // all CTAs co-resident (<= SM count)

// Scratch (static device arrays: allowed; no cudaMalloc anywhere)
__device__ float    g_gates[(size_t)T_STEPS * BATCH * G4];   // [t*B+b][g] (256 MB)
__device__ float    g_part[4 * BATCH * G4];                  // [kc][b][g] (2 MB)
__device__ uint16_t g_yhi[BATCH * HDIM];                     // y as bf16 hi
__device__ uint16_t g_ylo[BATCH * HDIM];                     // y as bf16 lo

// Grid-barrier state (sense-reversing; even barrier count per launch -> clean replays)
__device__ int               g_bar_count = 0;
__device__ volatile unsigned g_bar_sense = 0;

__device__ __forceinline__ float hsig(float x) {
    return fminf(fmaxf(x * (1.0f / 6.0f) + 0.5f, 0.0f), 1.0f);
}
__device__ __forceinline__ float htanh(float x) {
    return fminf(fmaxf(x, -1.0f), 1.0f);
}

// Split two floats into packed bf16 hi-pair and lo-pair (v = hi + lo)
__device__ __forceinline__ void split2(float x, float y, uint32_t& hi, uint32_t& lo) {
    const __nv_bfloat16 hx = __float2bfloat16_rn(x);
    const __nv_bfloat16 hy = __float2bfloat16_rn(y);
    const float fx = __bfloat162float(hx);
    const float fy = __bfloat162float(hy);
    const __nv_bfloat16 lx = __float2bfloat16_rn(x - fx);
    const __nv_bfloat16 ly = __float2bfloat16_rn(y - fy);
    hi = (uint32_t)__bfloat16_as_ushort(hx) | ((uint32_t)__bfloat16_as_ushort(hy) << 16);
    lo = (uint32_t)__bfloat16_as_ushort(lx) | ((uint32_t)__bfloat16_as_ushort(ly) << 16);
}

// D += A(16x16,row) * B(16x8,col)  bf16 -> fp32
__device__ __forceinline__ void mma16816(float* c, uint32_t a0, uint32_t a1,
                                         uint32_t a2, uint32_t a3,
                                         uint32_t b0, uint32_t b1) {
    asm volatile(
        "mma.sync.aligned.m16n8k16.row.col.f32.bf16.bf16.f32 "
        "{%0,%1,%2,%3}, {%4,%5,%6,%7}, {%8,%9}, {%0,%1,%2,%3};"
        : "+f"(c[0]), "+f"(c[1]), "+f"(c[2]), "+f"(c[3])
        : "r"(a0), "r"(a1), "r"(a2), "r"(a3), "r"(b0), "r"(b1));
}

__device__ __forceinline__ void grid_barrier(unsigned* local_sense) {
    __threadfence();
    __syncthreads();
    if (threadIdx.x == 0) {
        const unsigned s = *local_sense ^ 1u;
        *local_sense = s;
        if (atomicAdd(&g_bar_count, 1) == GRID_SCAN - 1) {
            g_bar_count = 0;
            __threadfence();
            g_bar_sense = s;
        } else {
            while (g_bar_sense != s) { }
        }
    }
    __syncthreads();
}

// ===========================================================================
// Kernel A: gates_pre[m][n] = sum_k x[m][k]*W[n][k] + bias[n]   (HMMA bf16x3)
// M=16384, N=4096, K=1024.  CTA tile 128x128, BK=32, 8 warps (4m x 2n).
// ===========================================================================
#define SA 40   // smem row stride (elems), padded: conflict-free fragment LDS

__global__ __launch_bounds__(256) void gemm_gates_mma(
    const float* __restrict__ x, const float* __restrict__ W,
    const float* __restrict__ bW, const float* __restrict__ bR)
{
    __shared__ uint16_t Ah[128 * SA], Al[128 * SA], Bh[128 * SA], Bl[128 * SA];
    __shared__ float biasS[128];

    const int tid  = threadIdx.x;
    const int lane = tid & 31;
    const int wid  = tid >> 5;
    const int wm   = wid & 3;     // 0..3 -> 32 m-rows each
    const int wn   = wid >> 2;    // 0..1 -> 64 n-cols each
    const int mblk = blockIdx.y;  // 0..127
    const int nblk = blockIdx.x;  // 0..31

    if (tid < 128) biasS[tid] = bW[nblk * 128 + tid] + bR[nblk * 128 + tid];

    const float* xb = x + (size_t)(mblk * 128) * IDIM;
    const float* wb = W + (size_t)(nblk * 128) * IDIM;

    float c[2][8][4];
#pragma unroll
    for (int mt = 0; mt < 2; mt++)
#pragma unroll
        for (int nt = 0; nt < 8; nt++)
#pragma unroll
            for (int q = 0; q < 4; q++) c[mt][nt][q] = 0.0f;

    for (int k0 = 0; k0 < IDIM; k0 += 32) {
        // Stage gmem tiles (128x32 each) into registers
        float4 av[4], bv[4];
#pragma unroll
        for (int i = 0; i < 4; i++) {
            const int idx = tid + 256 * i;
            const int row = idx >> 3, c4 = (idx & 7) * 4;
            av[i] = __ldg((const float4*)(xb + (size_t)row * IDIM + k0 + c4));
            bv[i] = __ldg((const float4*)(wb + (size_t)row * IDIM + k0 + c4));
        }
        __syncthreads();
#pragma unroll
        for (int i = 0; i < 4; i++) {
            const int idx = tid + 256 * i;
            const int row = idx >> 3, c4 = (idx & 7) * 4;
            uint32_t h0, l0, h1, l1;
            split2(av[i].x, av[i].y, h0, l0);
            split2(av[i].z, av[i].w, h1, l1);
            *(uint2*)&Ah[row * SA + c4] = make_uint2(h0, h1);
            *(uint2*)&Al[row * SA + c4] = make_uint2(l0, l1);
            split2(bv[i].x, bv[i].y, h0, l0);
            split2(bv[i].z, bv[i].w, h1, l1);
            *(uint2*)&Bh[row * SA + c4] = make_uint2(h0, h1);
            *(uint2*)&Bl[row * SA + c4] = make_uint2(l0, l1);
        }
        __syncthreads();

#pragma unroll
        for (int kk = 0; kk < 32; kk += 16) {
            uint32_t ah[2][4], al[2][4];
#pragma unroll
            for (int mt = 0; mt < 2; mt++) {
                const int ra = wm * 32 + mt * 16 + (lane >> 2);
                const int ca = kk + (lane & 3) * 2;
                ah[mt][0] = *(const uint32_t*)&Ah[ra * SA + ca];
                ah[mt][1] = *(const uint32_t*)&Ah[(ra + 8) * SA + ca];
                ah[mt][2] = *(const uint32_t*)&Ah[ra * SA + ca + 8];
                ah[mt][3] = *(const uint32_t*)&Ah[(ra + 8) * SA + ca + 8];
                al[mt][0] = *(const uint32_t*)&Al[ra * SA + ca];
                al[mt][1] = *(const uint32_t*)&Al[(ra + 8) * SA + ca];
                al[mt][2] = *(const uint32_t*)&Al[ra * SA + ca + 8];
                al[mt][3] = *(const uint32_t*)&Al[(ra + 8) * SA + ca + 8];
            }
#pragma unroll
            for (int nt = 0; nt < 8; nt++) {
                const int rb = wn * 64 + nt * 8 + (lane >> 2);
                const int cb = kk + (lane & 3) * 2;
                const uint32_t bh0 = *(const uint32_t*)&Bh[rb * SA + cb];
                const uint32_t bh1 = *(const uint32_t*)&Bh[rb * SA + cb + 8];
                const uint32_t bl0 = *(const uint32_t*)&Bl[rb * SA + cb];
                const uint32_t bl1 = *(const uint32_t*)&Bl[rb * SA + cb + 8];
#pragma unroll
                for (int mt = 0; mt < 2; mt++) {
                    mma16816(c[mt][nt], ah[mt][0], ah[mt][1], ah[mt][2], ah[mt][3], bh0, bh1);
                    mma16816(c[mt][nt], al[mt][0], al[mt][1], al[mt][2], al[mt][3], bh0, bh1);
                    mma16816(c[mt][nt], ah[mt][0], ah[mt][1], ah[mt][2], ah[mt][3], bl0, bl1);
                }
            }
        }
        __syncthreads();
    }

    // Epilogue: c0,c1 -> (row, col..col+1), c2,c3 -> (row+8, col..col+1)
#pragma unroll
    for (int mt = 0; mt < 2; mt++) {
#pragma unroll
        for (int nt = 0; nt < 8; nt++) {
            const int r0 = mblk * 128 + wm * 32 + mt * 16 + (lane >> 2);
            const int nl = wn * 64 + nt * 8 + (lane & 3) * 2;
            const float b0 = biasS[nl], b1 = biasS[nl + 1];
            *(float2*)&g_gates[(size_t)r0 * G4 + nblk * 128 + nl] =
                make_float2(c[mt][nt][0] + b0, c[mt][nt][1] + b1);
            *(float2*)&g_gates[(size_t)(r0 + 8) * G4 + nblk * 128 + nl] =
                make_float2(c[mt][nt][2] + b0, c[mt][nt][3] + b1);
        }
    }
}

// ===========================================================================
// Kernel B: persistent scan with HMMA recurrent GEMM.
//   CTA (mblk = bid&31, kc = bid>>5).  R chunk [128 g][256 k] held in SMEM as
//   bf16 hi/lo for ALL 512 steps.  Per step:
//     phase 1: D[b][g] = sum_k y[b][k]*R[g][k] over this k-chunk  (HMMA bf16x3)
//              y chunk loaded from g_yhi/g_ylo (bf16, written in phase 2).
//     phase 2: combine 4 partials + gates_pre, nonlinearities, update y/c,
//              emit y as bf16 hi/lo for the next step.
// Dynamic smem: Rh[128][264] Rl[128][264] Yh[32][264] Yl[32][264] (165 KB).
// ===========================================================================
#define SR 264  // smem row stride (elems) for scan tiles
#define SM_RH 0
#define SM_RL (128 * SR * 2)
#define SM_YH (2 * 128 * SR * 2)
#define SM_YL (2 * 128 * SR * 2 + 32 * SR * 2)
#define SM_SCAN_TOTAL (2 * 128 * SR * 2 + 2 * 32 * SR * 2)

__global__ __launch_bounds__(256) void lstm_scan(
    const float* __restrict__ R, const float* __restrict__ y0,
    const float* __restrict__ c0, float* __restrict__ yout,
    float* __restrict__ cout)
{
    extern __shared__ char smem[];
    uint16_t* Rh = (uint16_t*)(smem + SM_RH);
    uint16_t* Rl = (uint16_t*)(smem + SM_RL);
    uint16_t* Yh = (uint16_t*)(smem + SM_YH);
    uint16_t* Yl = (uint16_t*)(smem + SM_YL);
    __shared__ unsigned bar_sense;

    const int tid  = threadIdx.x;
    const int lane = tid & 31;
    const int wid  = tid >> 5;
    const int bid  = blockIdx.x;
    const int mblk = bid & 31;   // g-tile (128 gate-rows)
    const int kc   = bid >> 5;   // k-chunk (256)

    if (tid == 0) bar_sense = 0;

    // ---- One-time: convert R chunk to bf16 hi/lo in SMEM ----
    {
        const float* Rb = R + (size_t)(mblk * 128) * HDIM + kc * 256;
#pragma unroll 8
        for (int i = 0; i < 64; i++) {
            const int p = tid + 256 * i;        // pair index, 16384 total
            const int row = p >> 7, cp = (p & 127) * 2;
            const float2 v = __ldg((const float2*)(Rb + (size_t)row * HDIM + cp));
            uint32_t hi, lo;
            split2(v.x, v.y, hi, lo);
            *(uint32_t*)&Rh[row * SR + cp] = hi;
            *(uint32_t*)&Rl[row * SR + cp] = lo;
        }
    }

    // ---- One-time: publish y0 as bf16 hi/lo ----
    const int cn = bid * 256 + tid;   // 0..32767 -> (b,h)
    const int cb = cn >> 10;
    const int ch = cn & 1023;
    {
        const float v = y0[cn];
        const __nv_bfloat16 h = __float2bfloat16_rn(v);
        g_yhi[cn] = __bfloat16_as_ushort(h);
        g_ylo[cn] = __bfloat16_as_ushort(__float2bfloat16_rn(v - __bfloat162float(h)));
    }

    grid_barrier(&bar_sense);   // barrier #1

    float* part = g_part + (size_t)kc * BATCH * G4;

    for (int t = 0; t < T_STEPS; t++) {
        // -------- phase 1a: load y chunk (bf16 hi/lo) into SMEM --------
#pragma unroll 4
        for (int i = 0; i < 16; i++) {
            const int p = tid + 256 * i;        // 4096 pairs (32 x 128)
            const int b = p >> 7, cp = (p & 127) * 2;
            const int gs = b * HDIM + kc * 256 + cp;
            *(uint32_t*)&Yh[b * SR + cp] = __ldcg((const uint32_t*)(g_yhi + gs));
            *(uint32_t*)&Yl[b * SR + cp] = __ldcg((const uint32_t*)(g_ylo + gs));
        }
        __syncthreads();

        // -------- phase 1b: HMMA  D[b][g] (M=32, N=128, K=256) --------
        // warp wid owns g columns [wid*16, wid*16+16): 2 n8-subtiles, both m16 tiles
        float c[2][2][4];
#pragma unroll
        for (int mt = 0; mt < 2; mt++)
#pragma unroll
            for (int nt = 0; nt < 2; nt++)
#pragma unroll
                for (int q = 0; q < 4; q++) c[mt][nt][q] = 0.0f;

#pragma unroll 4
        for (int kk = 0; kk < 256; kk += 16) {
            uint32_t ah[2][4], al[2][4];
#pragma unroll
            for (int mt = 0; mt < 2; mt++) {
                const int ra = mt * 16 + (lane >> 2);
                const int ca = kk + (lane & 3) * 2;
                ah[mt][0] = *(const uint32_t*)&Yh[ra * SR + ca];
                ah[mt][1] = *(const uint32_t*)&Yh[(ra + 8) * SR + ca];
                ah[mt][2] = *(const uint32_t*)&Yh[ra * SR + ca + 8];
                ah[mt][3] = *(const uint32_t*)&Yh[(ra + 8) * SR + ca + 8];
                al[mt][0] = *(const uint32_t*)&Yl[ra * SR + ca];
                al[mt][1] = *(const uint32_t*)&Yl[(ra + 8) * SR + ca];
                al[mt][2] = *(const uint32_t*)&Yl[ra * SR + ca + 8];
                al[mt][3] = *(const uint32_t*)&Yl[(ra + 8) * SR + ca + 8];
            }
#pragma unroll
            for (int nt = 0; nt < 2; nt++) {
                const int rb = wid * 16 + nt * 8 + (lane >> 2);
                const int cb = kk + (lane & 3) * 2;
                const uint32_t bh0 = *(const uint32_t*)&Rh[rb * SR + cb];
                const uint32_t bh1 = *(const uint32_t*)&Rh[rb * SR + cb + 8];
                const uint32_t bl0 = *(const uint32_t*)&Rl[rb * SR + cb];
                const uint32_t bl1 = *(const uint32_t*)&Rl[rb * SR + cb + 8];
#pragma unroll
                for (int mt = 0; mt < 2; mt++) {
                    mma16816(c[mt][nt], ah[mt][0], ah[mt][1], ah[mt][2], ah[mt][3], bh0, bh1);
                    mma16816(c[mt][nt], al[mt][0], al[mt][1], al[mt][2], al[mt][3], bh0, bh1);
                    mma16816(c[mt][nt], ah[mt][0], ah[mt][1], ah[mt][2], ah[mt][3], bl0, bl1);
                }
            }
        }

        // store partials: c0,c1 -> b=(mt*16+lane/4), g pair; c2,c3 -> b+8
#pragma unroll
        for (int mt = 0; mt < 2; mt++) {
#pragma unroll
            for (int nt = 0; nt < 2; nt++) {
                const int b0 = mt * 16 + (lane >> 2);
                const int g0 = mblk * 128 + wid * 16 + nt * 8 + (lane & 3) * 2;
                *(float2*)&part[(size_t)b0 * G4 + g0] =
                    make_float2(c[mt][nt][0], c[mt][nt][1]);
                *(float2*)&part[(size_t)(b0 + 8) * G4 + g0] =
                    make_float2(c[mt][nt][2], c[mt][nt][3]);
            }
        }

        grid_barrier(&bar_sense);

        // -------- phase 2: combine + nonlinearities + state update --------
        {
            const float* gb = g_gates + ((size_t)t * BATCH + cb) * G4;
            float gi = __ldg(gb + ch);
            float gf = __ldg(gb + HDIM + ch);
            float gz = __ldg(gb + 2 * HDIM + ch);
            float go = __ldg(gb + 3 * HDIM + ch);

#pragma unroll
            for (int q = 0; q < 4; q++) {
                const float* p = g_part + (size_t)q * BATCH * G4 + (size_t)cb * G4;
                gi += __ldcg(p + ch);
                gf += __ldcg(p + HDIM + ch);
                gz += __ldcg(p + 2 * HDIM + ch);
                go += __ldcg(p + 3 * HDIM + ch);
            }

            const float* cprev = t ? (cout + (size_t)(t - 1) * BATCH * HDIM) : c0;
            const float cp = __ldcg(cprev + cn);

            const float i_ = hsig(gi);
            const float f_ = hsig(gf);
            const float z_ = htanh(gz);
            const float o_ = hsig(go);

            const float c_new = f_ * cp + i_ * z_;
            const float y_new = o_ * htanh(c_new);

            yout[(size_t)t * BATCH * HDIM + cn] = y_new;
            cout[(size_t)t * BATCH * HDIM + cn] = c_new;

            const __nv_bfloat16 h = __float2bfloat16_rn(y_new);
            g_yhi[cn] = __bfloat16_as_ushort(h);
            g_ylo[cn] = __bfloat16_as_ushort(
                __float2bfloat16_rn(y_new - __bfloat162float(h)));
        }

        grid_barrier(&bar_sense);
    }

    grid_barrier(&bar_sense);   // closing barrier -> even total (1026), clean replay
}

// ===========================================================================
// Launch: 2 graph nodes.
// ===========================================================================
extern "C" void kernel_launch(void* const* d_in, const int* in_sizes, int n_in,
                              void* d_out, int out_size)
{
    const float* y0 = (const float*)d_in[0];
    const float* c0 = (const float*)d_in[1];
    const float* x  = (const float*)d_in[2];
    const float* W  = (const float*)d_in[3];
    const float* R  = (const float*)d_in[4];
    const float* bW = (const float*)d_in[5];
    const float* bR = (const float*)d_in[6];

    float* yout = (float*)d_out;                                   // [T,B,H]
    float* cout = yout + (size_t)T_STEPS * BATCH * HDIM;           // [T,B,H]

    cudaFuncSetAttribute(lstm_scan,
                         cudaFuncAttributeMaxDynamicSharedMemorySize,
                         SM_SCAN_TOTAL);

    // Input projection for all timesteps (HMMA bf16x3)
    gemm_gates_mma<<<dim3(32, 128), 256>>>(x, W, bW, bR);

    // Full sequential scan in one persistent kernel (HMMA recurrent GEMM)
    lstm_scan<<<GRID_SCAN, 256, SM_SCAN_TOTAL>>>(R, y0, c0, yout, cout);
}